// round 11
// baseline (speedup 1.0000x reference)
#include <cuda_runtime.h>
#include <cstdint>

// ---------------- problem dims ----------------
#define NTOK 4096
#define CDIM 1024
#define ENUM 8
#define HDIM 512
#define HSDIM 2048

// ---------------- GEMM tiling (round-8 proven config) ----------------
#define BM 128
#define BK 32
#define AST 40                        // smem row stride: bank stride 8 -> conflict-free LDS.64
#define STG (BM * AST)                // 5120 floats = 20KB per operand stage
#define SMEMB (4 * STG * 4)           // 81920 B (2 stages x (A+B))

// k-pair permutation within each 8-wide k-group: storage order [0,4,1,5,2,6,3,7]
__device__ __forceinline__ int pk8(int c) { return ((c & 3) << 1) | ((c >> 2) & 1); }

// ---------------- device scratch ----------------
__device__ int   d_cnt[ENUM];
__device__ int   d_tok[ENUM][NTOK];
__device__ float d_gate[ENUM][NTOK];
__device__ int   d_eslot[NTOK][2];
__device__ float d_hid [ENUM*NTOK*HDIM];    // k-paired tf32 hidden
__device__ float d_pair[ENUM*NTOK*CDIM];    // gate-scaled expert out (canonical)
__device__ float d_sh  [NTOK*HSDIM];        // k-paired tf32 shared hidden
__device__ float d_xr  [NTOK*CDIM];         // k-paired tf32 x
__device__ float d_guT [ENUM*2*HDIM*CDIM];  // [E][2H][C] transposed, k-paired
__device__ float d_dwT [ENUM*CDIM*HDIM];    // [E][C][H] transposed, k-paired
__device__ float d_sgwr[HSDIM*CDIM];        // k-paired
__device__ float d_suwr[HSDIM*CDIM];        // k-paired
__device__ float d_sdwr[CDIM*HSDIM];        // k-paired

// ---------------- helpers ----------------
__device__ __forceinline__ float tf32r(float f) {
    uint32_t u; asm("cvt.rna.tf32.f32 %0, %1;" : "=r"(u) : "f"(f));
    return __uint_as_float(u);
}
__device__ __forceinline__ void cp16(float* s, const float* g) {
    uint32_t sa = (uint32_t)__cvta_generic_to_shared(s);
    asm volatile("cp.async.cg.shared.global [%0], [%1], 16;" :: "r"(sa), "l"(g));
}
__device__ __forceinline__ void mma8(float* d, const uint32_t* a, const uint32_t* b) {
    asm volatile(
        "mma.sync.aligned.m16n8k8.row.col.f32.tf32.tf32.f32 "
        "{%0,%1,%2,%3},{%4,%5,%6,%7},{%8,%9},{%0,%1,%2,%3};"
        : "+f"(d[0]), "+f"(d[1]), "+f"(d[2]), "+f"(d[3])
        : "r"(a[0]), "r"(a[1]), "r"(a[2]), "r"(a[3]), "r"(b[0]), "r"(b[1]));
}
__device__ __forceinline__ float silu_f(float v) { return v / (1.f + expf(-v)); }

// ---------------- router: logits/top2/gates only (vectorized) -------------------
__global__ void router_kernel(const float* __restrict__ x, const float* __restrict__ rw) {
    int t = blockIdx.x * (blockDim.x >> 5) + (threadIdx.x >> 5);
    int lane = threadIdx.x & 31;
    if (t >= NTOK) return;
    const float4* xr = (const float4*)(x + (long long)t * CDIM);
    float acc[ENUM];
#pragma unroll
    for (int e = 0; e < ENUM; e++) acc[e] = 0.f;
#pragma unroll
    for (int i = lane; i < CDIM / 4; i += 32) {   // 8 iterations
        float4 xv = xr[i];
#pragma unroll
        for (int e = 0; e < ENUM; e++) {
            float4 wv = ((const float4*)(rw + e * CDIM))[i];
            acc[e] += xv.x * wv.x + xv.y * wv.y + xv.z * wv.z + xv.w * wv.w;
        }
    }
#pragma unroll
    for (int e = 0; e < ENUM; e++)
#pragma unroll
        for (int off = 16; off; off >>= 1) acc[e] += __shfl_xor_sync(~0u, acc[e], off);
    if (lane == 0) {
        int i0 = 0; float v0 = acc[0];
#pragma unroll
        for (int e = 1; e < ENUM; e++) if (acc[e] > v0) { v0 = acc[e]; i0 = e; }
        int i1 = -1; float v1 = -3.0e38f;
#pragma unroll
        for (int e = 0; e < ENUM; e++) if (e != i0 && acc[e] > v1) { v1 = acc[e]; i1 = e; }
        float g0 = 1.f / (1.f + expf(-v0));
        float g1 = 1.f / (1.f + expf(-v1));
        int s0 = atomicAdd(&d_cnt[i0], 1);
        int s1 = atomicAdd(&d_cnt[i1], 1);
        d_tok[i0][s0] = t; d_gate[i0][s0] = g0; d_eslot[t][0] = i0 * NTOK + s0;
        d_tok[i1][s1] = t; d_gate[i1][s1] = g1; d_eslot[t][1] = i1 * NTOK + s1;
    }
}

// ---------------- preprocessing ----------------
// single-array round + k-pair permute (one 8-group per thread)
__global__ void round_perm1(const float* __restrict__ src, float* __restrict__ dst) {
    long long g = (long long)blockIdx.x * 256 + threadIdx.x;
    float4 a = ((const float4*)src)[g * 2];
    float4 b = ((const float4*)src)[g * 2 + 1];
    ((float4*)dst)[g * 2]     = make_float4(tf32r(a.x), tf32r(b.x), tf32r(a.y), tf32r(b.y));
    ((float4*)dst)[g * 2 + 1] = make_float4(tf32r(a.z), tf32r(b.z), tf32r(a.w), tf32r(b.w));
}
__global__ void round_perm3(const float* __restrict__ s0, float* __restrict__ d0,
                            const float* __restrict__ s1, float* __restrict__ d1,
                            const float* __restrict__ s2, float* __restrict__ d2) {
    const float* src = (blockIdx.y == 0) ? s0 : (blockIdx.y == 1) ? s1 : s2;
    float*       dst = (blockIdx.y == 0) ? d0 : (blockIdx.y == 1) ? d1 : d2;
    long long g = (long long)blockIdx.x * 256 + threadIdx.x;
    float4 a = ((const float4*)src)[g * 2];
    float4 b = ((const float4*)src)[g * 2 + 1];
    ((float4*)dst)[g * 2]     = make_float4(tf32r(a.x), tf32r(b.x), tf32r(a.y), tf32r(b.y));
    ((float4*)dst)[g * 2 + 1] = make_float4(tf32r(a.z), tf32r(b.z), tf32r(a.w), tf32r(b.w));
}
// dst[z][c][perm(r)] = rna(src[z][r][c])
__global__ void transpose_rna_perm(const float* __restrict__ src, float* __restrict__ dst,
                                   int R, int C) {
    __shared__ float tile[32][33];
    long long zo = (long long)blockIdx.z * R * C;
    int r0 = blockIdx.y * 32, c0 = blockIdx.x * 32;
    int tx = threadIdx.x, ty = threadIdx.y;
#pragma unroll
    for (int i = 0; i < 32; i += 8)
        tile[ty + i][tx] = src[zo + (long long)(r0 + ty + i) * C + c0 + tx];
    __syncthreads();
    int rp = r0 + ((tx & ~7) | pk8(tx & 7));
#pragma unroll
    for (int i = 0; i < 32; i += 8)
        dst[zo + (long long)(c0 + ty + i) * R + rp] = tf32r(tile[tx][ty + i]);
}

// ---------------- phase 1: fused SwiGLU GEMMs (templated expert/shared) ---------
// CTA: 128 threads (2x2 warps). Tile: 128 rows x 64 hidden cols.
template <bool EXPERT>
__global__ __launch_bounds__(128) void phase1_kernel(
    const float* __restrict__ xr, const float* __restrict__ guT,
    const float* __restrict__ sgw, const float* __restrict__ suw,
    float* __restrict__ hid, float* __restrict__ sh)
{
    const int bid = blockIdx.x;
    const float *B1, *B2;
    float* C; int ldc, z = 0, bm, bn;
    if (EXPERT) {
        z = bid >> 8; int rem = bid & 255; bm = rem >> 3; bn = rem & 7;
        if (bm * BM >= d_cnt[z]) return;
        B1 = guT + (long long)z * 2 * HDIM * CDIM + (long long)(bn * 64) * CDIM;
        B2 = B1 + (long long)HDIM * CDIM;
        C  = hid + (long long)z * NTOK * HDIM;
        ldc = HDIM;
    } else {
        bm = bid >> 5; bn = bid & 31;
        B1 = sgw + (long long)(bn * 64) * CDIM;
        B2 = suw + (long long)(bn * 64) * CDIM;
        C  = sh;
        ldc = HSDIM;
    }
    const int K = CDIM;

    extern __shared__ __align__(16) float smem[];
    float* sA = smem;                   // [2][128][AST]
    float* sB = smem + 2 * STG;         // [2][128][AST]  rows 0-63 gate, 64-127 up

    const int tid = threadIdx.x, lane = tid & 31, w = tid >> 5;
    const int ly = lane >> 2, lx = lane & 3;
    const int wm = w >> 1, wn = w & 1;  // 2 x 2 warps

    const float* aPtr[8];
    const float* bPtr[8];
    const int rbase = tid >> 3, kc = (tid & 7) * 4;
#pragma unroll
    for (int c = 0; c < 8; c++) {
        int row = rbase + 16 * c;
        long long arow = EXPERT ? (long long)d_tok[z][bm * BM + row] : (long long)(bm * BM + row);
        aPtr[c] = xr + arow * K;
        bPtr[c] = ((row < 64) ? (B1 + (long long)row * K) : (B2 + (long long)(row - 64) * K));
    }
    auto loadStage = [&](int st, int k0) {
        float* dA = sA + st * STG;
        float* dB = sB + st * STG;
#pragma unroll
        for (int c = 0; c < 8; c++) {
            int row = rbase + 16 * c;
            cp16(dA + row * AST + kc, aPtr[c] + k0 + kc);
            cp16(dB + row * AST + kc, bPtr[c] + k0 + kc);
        }
        asm volatile("cp.async.commit_group;");
    };

    float accG[4][4][4], accU[4][4][4];
#pragma unroll
    for (int a = 0; a < 4; a++)
#pragma unroll
        for (int b = 0; b < 4; b++)
#pragma unroll
            for (int q = 0; q < 4; q++) { accG[a][b][q] = 0.f; accU[a][b][q] = 0.f; }

    const int nk = K / BK;
    loadStage(0, 0);

    for (int kt = 0; kt < nk; kt++) {
        const int st = kt & 1;
        asm volatile("cp.async.wait_group 0;");
        __syncthreads();
        if (kt + 1 < nk) loadStage((kt + 1) & 1, (kt + 1) * BK);

        const float* cA = sA + st * STG;
        const float* cB = sB + st * STG;
#pragma unroll
        for (int ks = 0; ks < 4; ks++) {
            const int kb = ks * 8;
            uint32_t af[4][4], bg[4][2], bu[4][2];
#pragma unroll
            for (int im = 0; im < 4; im++) {
                int r = wm * 64 + im * 16;
                float2 v0 = *(const float2*)(cA + (r     + ly) * AST + kb + 2 * lx);
                float2 v1 = *(const float2*)(cA + (r + 8 + ly) * AST + kb + 2 * lx);
                af[im][0] = __float_as_uint(v0.x); af[im][2] = __float_as_uint(v0.y);
                af[im][1] = __float_as_uint(v1.x); af[im][3] = __float_as_uint(v1.y);
            }
#pragma unroll
            for (int in = 0; in < 4; in++) {
                int cn = wn * 32 + in * 8 + ly;
                float2 g = *(const float2*)(cB + cn * AST + kb + 2 * lx);
                float2 u = *(const float2*)(cB + (64 + cn) * AST + kb + 2 * lx);
                bg[in][0] = __float_as_uint(g.x); bg[in][1] = __float_as_uint(g.y);
                bu[in][0] = __float_as_uint(u.x); bu[in][1] = __float_as_uint(u.y);
            }
#pragma unroll
            for (int im = 0; im < 4; im++)
#pragma unroll
                for (int in = 0; in < 4; in++) {
                    mma8(accG[im][in], af[im], bg[in]);
                    mma8(accU[im][in], af[im], bu[in]);
                }
        }
    }

    // epilogue: out = rna(silu(g)*u), k-paired layout
    const int off0 = pk8(2 * lx);
#pragma unroll
    for (int im = 0; im < 4; im++) {
        int rr = bm * BM + wm * 64 + im * 16 + ly;
#pragma unroll
        for (int in = 0; in < 4; in++) {
            long long base = (long long)rr * ldc + bn * 64 + wn * 32 + in * 8;
            float* g = accG[im][in];
            float* u = accU[im][in];
            C[base + off0]                 = tf32r(silu_f(g[0]) * u[0]);
            C[base + off0 + 2]             = tf32r(silu_f(g[1]) * u[1]);
            C[base + 8LL * ldc + off0]     = tf32r(silu_f(g[2]) * u[2]);
            C[base + 8LL * ldc + off0 + 2] = tf32r(silu_f(g[3]) * u[3]);
        }
    }
}

// ---------------- phase 2: down GEMMs (templated expert/shared) ------------------
// CTA: 128 threads (2x2 warps). Tile: 128 x 128. Warp: 64 x 64.
template <bool EXPERT>
__global__ __launch_bounds__(128) void phase2_kernel(
    const float* __restrict__ hid, const float* __restrict__ dwT,
    const float* __restrict__ sh,  const float* __restrict__ sdw,
    float* __restrict__ pair, float* __restrict__ out)
{
    const int bid = blockIdx.x;
    const float *A, *B; const float* gate; float* C;
    int K, z = 0, bm, bn;
    if (EXPERT) {
        z = bid >> 8; int rem = bid & 255; bm = rem >> 3; bn = rem & 7;
        if (bm * BM >= d_cnt[z]) return;
        A = hid + (long long)z * NTOK * HDIM;
        K = HDIM;
        B = dwT + (long long)z * CDIM * HDIM + (long long)(bn * 128) * HDIM;
        C = pair + (long long)z * NTOK * CDIM;
        gate = d_gate[z];
    } else {
        bm = bid >> 3; bn = bid & 7;
        A = sh; K = HSDIM;
        B = sdw + (long long)(bn * 128) * HSDIM;
        C = out;
        gate = nullptr;
    }

    extern __shared__ __align__(16) float smem[];
    float* sA = smem;                   // [2][128][AST]
    float* sB = smem + 2 * STG;         // [2][128][AST]

    const int tid = threadIdx.x, lane = tid & 31, w = tid >> 5;
    const int ly = lane >> 2, lx = lane & 3;
    const int wm = w >> 1, wn = w & 1;  // 2 x 2 warps, each 64x64

    const int rbase = tid >> 3, kc = (tid & 7) * 4;
    const float* aBase = A + (long long)(bm * BM + rbase) * K;
    const float* bBase = B + (long long)rbase * K;

    auto loadStage = [&](int st, int k0) {
        float* dA = sA + st * STG;
        float* dB = sB + st * STG;
#pragma unroll
        for (int c = 0; c < 8; c++) {
            int row = rbase + 16 * c;
            cp16(dA + row * AST + kc, aBase + (long long)(16 * c) * K + k0 + kc);
            cp16(dB + row * AST + kc, bBase + (long long)(16 * c) * K + k0 + kc);
        }
        asm volatile("cp.async.commit_group;");
    };

    float acc[4][8][4];
#pragma unroll
    for (int a = 0; a < 4; a++)
#pragma unroll
        for (int b = 0; b < 8; b++)
#pragma unroll
            for (int q = 0; q < 4; q++) acc[a][b][q] = 0.f;

    const int nk = K / BK;
    loadStage(0, 0);

    for (int kt = 0; kt < nk; kt++) {
        const int st = kt & 1;
        asm volatile("cp.async.wait_group 0;");
        __syncthreads();
        if (kt + 1 < nk) loadStage((kt + 1) & 1, (kt + 1) * BK);

        const float* cA = sA + st * STG;
        const float* cB = sB + st * STG;
#pragma unroll
        for (int ks = 0; ks < 4; ks++) {
            const int kb = ks * 8;
            uint32_t af[4][4], bf[8][2];
#pragma unroll
            for (int im = 0; im < 4; im++) {
                int r = wm * 64 + im * 16;
                float2 v0 = *(const float2*)(cA + (r     + ly) * AST + kb + 2 * lx);
                float2 v1 = *(const float2*)(cA + (r + 8 + ly) * AST + kb + 2 * lx);
                af[im][0] = __float_as_uint(v0.x); af[im][2] = __float_as_uint(v0.y);
                af[im][1] = __float_as_uint(v1.x); af[im][3] = __float_as_uint(v1.y);
            }
#pragma unroll
            for (int in = 0; in < 8; in++) {
                int cn = wn * 64 + in * 8 + ly;
                float2 bb = *(const float2*)(cB + cn * AST + kb + 2 * lx);
                bf[in][0] = __float_as_uint(bb.x); bf[in][1] = __float_as_uint(bb.y);
            }
#pragma unroll
            for (int im = 0; im < 4; im++)
#pragma unroll
                for (int in = 0; in < 8; in++)
                    mma8(acc[im][in], af[im], bf[in]);
        }
    }

    // epilogue (canonical layout, float2 stores)
#pragma unroll
    for (int im = 0; im < 4; im++) {
        int rr = bm * BM + wm * 64 + im * 16 + ly;
        float s0 = gate ? gate[rr] : 1.f;
        float s1 = gate ? gate[rr + 8] : 1.f;
#pragma unroll
        for (int in = 0; in < 8; in++) {
            long long base = (long long)rr * CDIM + bn * 128 + wn * 64 + in * 8 + lx * 2;
            *(float2*)(C + base)              = make_float2(acc[im][in][0] * s0, acc[im][in][1] * s0);
            *(float2*)(C + base + 8LL * CDIM) = make_float2(acc[im][in][2] * s1, acc[im][in][3] * s1);
        }
    }
}

// ---------------- final combine: out += gated expert pair ----------------
__global__ void combine_kernel(float* __restrict__ out) {
    long long i = (long long)blockIdx.x * 256 + threadIdx.x;
    int t = (int)(i >> 8), j = (int)(i & 255);
    int es0 = d_eslot[t][0], es1 = d_eslot[t][1];
    float4 o  = ((float4*)out)[i];
    float4 p0 = ((const float4*)d_pair)[(long long)es0 * 256 + j];
    float4 p1 = ((const float4*)d_pair)[(long long)es1 * 256 + j];
    o.x += p0.x + p1.x; o.y += p0.y + p1.y;
    o.z += p0.z + p1.z; o.w += p0.w + p1.w;
    ((float4*)out)[i] = o;
}

// ---------------- launch ----------------
extern "C" void kernel_launch(void* const* d_in, const int* in_sizes, int n_in,
                              void* d_out, int out_size) {
    const float* x   = (const float*)d_in[0];
    const float* rw  = (const float*)d_in[1];
    const float* guw = (const float*)d_in[2];
    const float* dw  = (const float*)d_in[3];
    const float* sgw = (const float*)d_in[4];
    const float* suw = (const float*)d_in[5];
    const float* sdw = (const float*)d_in[6];
    float* out = (float*)d_out;

    void* a;
    float *p_hid, *p_pair, *p_sh, *p_xr, *p_guT, *p_dwT, *p_sgwr, *p_suwr, *p_sdwr;
    cudaGetSymbolAddress(&a, d_hid);  p_hid  = (float*)a;
    cudaGetSymbolAddress(&a, d_pair); p_pair = (float*)a;
    cudaGetSymbolAddress(&a, d_sh);   p_sh   = (float*)a;
    cudaGetSymbolAddress(&a, d_xr);   p_xr   = (float*)a;
    cudaGetSymbolAddress(&a, d_guT);  p_guT  = (float*)a;
    cudaGetSymbolAddress(&a, d_dwT);  p_dwT  = (float*)a;
    cudaGetSymbolAddress(&a, d_sgwr); p_sgwr = (float*)a;
    cudaGetSymbolAddress(&a, d_suwr); p_suwr = (float*)a;
    cudaGetSymbolAddress(&a, d_sdwr); p_sdwr = (float*)a;
    void* cntAddr; cudaGetSymbolAddress(&cntAddr, d_cnt);

    static cudaStream_t s1 = nullptr, s2 = nullptr;
    static cudaEvent_t ev0 = nullptr, evG = nullptr, evD = nullptr, evP = nullptr,
                       evX = nullptr, evS = nullptr;
    if (!s1) {
        cudaStreamCreateWithFlags(&s1, cudaStreamNonBlocking);
        cudaStreamCreateWithFlags(&s2, cudaStreamNonBlocking);
        cudaEventCreateWithFlags(&ev0, cudaEventDisableTiming);
        cudaEventCreateWithFlags(&evG, cudaEventDisableTiming);
        cudaEventCreateWithFlags(&evD, cudaEventDisableTiming);
        cudaEventCreateWithFlags(&evP, cudaEventDisableTiming);
        cudaEventCreateWithFlags(&evX, cudaEventDisableTiming);
        cudaEventCreateWithFlags(&evS, cudaEventDisableTiming);
        cudaFuncSetAttribute(phase1_kernel<true >, cudaFuncAttributeMaxDynamicSharedMemorySize, SMEMB);
        cudaFuncSetAttribute(phase1_kernel<false>, cudaFuncAttributeMaxDynamicSharedMemorySize, SMEMB);
        cudaFuncSetAttribute(phase2_kernel<true >, cudaFuncAttributeMaxDynamicSharedMemorySize, SMEMB);
        cudaFuncSetAttribute(phase2_kernel<false>, cudaFuncAttributeMaxDynamicSharedMemorySize, SMEMB);
    }

    // ---- fork point ----
    cudaEventRecord(ev0, 0);
    cudaStreamWaitEvent(s1, ev0, 0);
    cudaStreamWaitEvent(s2, ev0, 0);

    // s2: k-paired tf32 x (front of the shared chain)
    round_perm1<<<NTOK * CDIM / 8 / 256, 256, 0, s2>>>(x, p_xr);
    cudaEventRecord(evX, s2);

    // s1: weight preprocessing
    transpose_rna_perm<<<dim3(2 * HDIM / 32, CDIM / 32, ENUM), dim3(32, 8), 0, s1>>>(guw, p_guT, CDIM, 2 * HDIM);
    cudaEventRecord(evG, s1);
    round_perm3<<<dim3(HSDIM * CDIM / 8 / 256, 3), 256, 0, s1>>>(sgw, p_sgwr, suw, p_suwr, sdw, p_sdwr);
    cudaEventRecord(evP, s1);
    transpose_rna_perm<<<dim3(CDIM / 32, HDIM / 32, ENUM), dim3(32, 8), 0, s1>>>(dw, p_dwT, HDIM, CDIM);
    cudaEventRecord(evD, s1);

    // main: router (logits/top2/gates only)
    cudaMemsetAsync(cntAddr, 0, sizeof(int) * ENUM, 0);
    router_kernel<<<NTOK / 8, 256, 0, 0>>>(x, rw);

    // expert chain on main: p1e -> p2e
    cudaStreamWaitEvent(0, evX, 0);
    cudaStreamWaitEvent(0, evG, 0);
    phase1_kernel<true><<<2048, 128, SMEMB, 0>>>(p_xr, p_guT, p_sgwr, p_suwr, p_hid, p_sh);
    cudaStreamWaitEvent(0, evD, 0);
    phase2_kernel<true><<<2048, 128, SMEMB, 0>>>(p_hid, p_dwT, p_sh, p_sdwr, p_pair, out);

    // shared chain on s2: p1s -> p2s (writes out base)
    cudaStreamWaitEvent(s2, evP, 0);
    phase1_kernel<false><<<1024, 128, SMEMB, s2>>>(p_xr, p_guT, p_sgwr, p_suwr, p_hid, p_sh);
    phase2_kernel<false><<<256, 128, SMEMB, s2>>>(p_hid, p_dwT, p_sh, p_sdwr, p_pair, out);
    cudaEventRecord(evS, s2);

    // ---- join: combine after both chains ----
    cudaStreamWaitEvent(0, evS, 0);
    combine_kernel<<<NTOK * CDIM / 4 / 256, 256, 0, 0>>>(out);

    (void)in_sizes; (void)n_in; (void)out_size;
}

// round 12
// speedup vs baseline: 1.0253x; 1.0253x over previous
#include <cuda_runtime.h>
#include <cstdint>

// ---------------- problem dims ----------------
#define NTOK 4096
#define CDIM 1024
#define ENUM 8
#define HDIM 512
#define HSDIM 2048

// ---------------- GEMM tiling (round-8 proven config) ----------------
#define BM 128
#define BK 32
#define AST 40                        // smem row stride: bank stride 8 -> conflict-free LDS.64
#define STG (BM * AST)                // 5120 floats = 20KB per operand stage
#define SMEMB (4 * STG * 4)           // 81920 B (2 stages x (A+B))

// k-pair permutation within each 8-wide k-group: storage order [0,4,1,5,2,6,3,7]
__device__ __forceinline__ int pk8(int c) { return ((c & 3) << 1) | ((c >> 2) & 1); }

// ---------------- device scratch ----------------
__device__ int   d_cnt[ENUM];
__device__ int   d_tok[ENUM][NTOK];
__device__ float d_gate[ENUM][NTOK];
__device__ int   d_eslot[NTOK][2];
__device__ float d_hid [ENUM*NTOK*HDIM];    // k-paired tf32 hidden
__device__ float d_pair[ENUM*NTOK*CDIM];    // gate-scaled expert out (canonical)
__device__ float d_sh  [NTOK*HSDIM];        // k-paired tf32 shared hidden
__device__ float d_xr  [NTOK*CDIM];         // k-paired tf32 x
__device__ float d_guT [ENUM*2*HDIM*CDIM];  // [E][2H][C] transposed, k-paired
__device__ float d_dwT [ENUM*CDIM*HDIM];    // [E][C][H] transposed, k-paired
__device__ float d_sgwr[HSDIM*CDIM];        // k-paired
__device__ float d_suwr[HSDIM*CDIM];        // k-paired
__device__ float d_sdwr[CDIM*HSDIM];        // k-paired

// ---------------- helpers ----------------
__device__ __forceinline__ float tf32r(float f) {
    uint32_t u; asm("cvt.rna.tf32.f32 %0, %1;" : "=r"(u) : "f"(f));
    return __uint_as_float(u);
}
__device__ __forceinline__ void cp16(float* s, const float* g) {
    uint32_t sa = (uint32_t)__cvta_generic_to_shared(s);
    asm volatile("cp.async.cg.shared.global [%0], [%1], 16;" :: "r"(sa), "l"(g));
}
__device__ __forceinline__ void mma8(float* d, const uint32_t* a, const uint32_t* b) {
    asm volatile(
        "mma.sync.aligned.m16n8k8.row.col.f32.tf32.tf32.f32 "
        "{%0,%1,%2,%3},{%4,%5,%6,%7},{%8,%9},{%0,%1,%2,%3};"
        : "+f"(d[0]), "+f"(d[1]), "+f"(d[2]), "+f"(d[3])
        : "r"(a[0]), "r"(a[1]), "r"(a[2]), "r"(a[3]), "r"(b[0]), "r"(b[1]));
}
__device__ __forceinline__ float silu_f(float v) { return v / (1.f + expf(-v)); }

// ---------------- router: vectorized logits/top2/gates + fused k-paired xr ------
__global__ void router_kernel(const float* __restrict__ x, const float* __restrict__ rw,
                              float* __restrict__ xw) {
    int t = blockIdx.x * (blockDim.x >> 5) + (threadIdx.x >> 5);
    int lane = threadIdx.x & 31;
    if (t >= NTOK) return;
    const float4* xr4 = (const float4*)(x + (long long)t * CDIM);
    float4* xo4 = (float4*)(xw + (long long)t * CDIM);
    float acc[ENUM];
#pragma unroll
    for (int e = 0; e < ENUM; e++) acc[e] = 0.f;
#pragma unroll
    for (int g = lane; g < CDIM / 8; g += 32) {   // 4 iterations, one 8-group each
        float4 av = xr4[2 * g];
        float4 bv = xr4[2 * g + 1];
#pragma unroll
        for (int e = 0; e < ENUM; e++) {
            float4 wa = ((const float4*)(rw + e * CDIM))[2 * g];
            float4 wb = ((const float4*)(rw + e * CDIM))[2 * g + 1];
            acc[e] += av.x * wa.x + av.y * wa.y + av.z * wa.z + av.w * wa.w
                    + bv.x * wb.x + bv.y * wb.y + bv.z * wb.z + bv.w * wb.w;
        }
        // k-paired tf32 store: group order [0,4,1,5,2,6,3,7]
        xo4[2 * g]     = make_float4(tf32r(av.x), tf32r(bv.x), tf32r(av.y), tf32r(bv.y));
        xo4[2 * g + 1] = make_float4(tf32r(av.z), tf32r(bv.z), tf32r(av.w), tf32r(bv.w));
    }
#pragma unroll
    for (int e = 0; e < ENUM; e++)
#pragma unroll
        for (int off = 16; off; off >>= 1) acc[e] += __shfl_xor_sync(~0u, acc[e], off);
    if (lane == 0) {
        int i0 = 0; float v0 = acc[0];
#pragma unroll
        for (int e = 1; e < ENUM; e++) if (acc[e] > v0) { v0 = acc[e]; i0 = e; }
        int i1 = -1; float v1 = -3.0e38f;
#pragma unroll
        for (int e = 0; e < ENUM; e++) if (e != i0 && acc[e] > v1) { v1 = acc[e]; i1 = e; }
        float g0 = 1.f / (1.f + expf(-v0));
        float g1 = 1.f / (1.f + expf(-v1));
        int s0 = atomicAdd(&d_cnt[i0], 1);
        int s1 = atomicAdd(&d_cnt[i1], 1);
        d_tok[i0][s0] = t; d_gate[i0][s0] = g0; d_eslot[t][0] = i0 * NTOK + s0;
        d_tok[i1][s1] = t; d_gate[i1][s1] = g1; d_eslot[t][1] = i1 * NTOK + s1;
    }
}

// ---------------- preprocessing ----------------
__global__ void round_perm3(const float* __restrict__ s0, float* __restrict__ d0,
                            const float* __restrict__ s1, float* __restrict__ d1,
                            const float* __restrict__ s2, float* __restrict__ d2) {
    const float* src = (blockIdx.y == 0) ? s0 : (blockIdx.y == 1) ? s1 : s2;
    float*       dst = (blockIdx.y == 0) ? d0 : (blockIdx.y == 1) ? d1 : d2;
    long long g = (long long)blockIdx.x * 256 + threadIdx.x;
    float4 a = ((const float4*)src)[g * 2];
    float4 b = ((const float4*)src)[g * 2 + 1];
    ((float4*)dst)[g * 2]     = make_float4(tf32r(a.x), tf32r(b.x), tf32r(a.y), tf32r(b.y));
    ((float4*)dst)[g * 2 + 1] = make_float4(tf32r(a.z), tf32r(b.z), tf32r(a.w), tf32r(b.w));
}
// dst[z][c][perm(r)] = rna(src[z][r][c])
__global__ void transpose_rna_perm(const float* __restrict__ src, float* __restrict__ dst,
                                   int R, int C) {
    __shared__ float tile[32][33];
    long long zo = (long long)blockIdx.z * R * C;
    int r0 = blockIdx.y * 32, c0 = blockIdx.x * 32;
    int tx = threadIdx.x, ty = threadIdx.y;
#pragma unroll
    for (int i = 0; i < 32; i += 8)
        tile[ty + i][tx] = src[zo + (long long)(r0 + ty + i) * C + c0 + tx];
    __syncthreads();
    int rp = r0 + ((tx & ~7) | pk8(tx & 7));
#pragma unroll
    for (int i = 0; i < 32; i += 8)
        dst[zo + (long long)(c0 + ty + i) * R + rp] = tf32r(tile[tx][ty + i]);
}

// ---------------- phase 1: fused SwiGLU GEMMs (templated expert/shared) ---------
// CTA: 128 threads (2x2 warps). Tile: 128 rows x 64 hidden cols.
template <bool EXPERT>
__global__ __launch_bounds__(128) void phase1_kernel(
    const float* __restrict__ xr, const float* __restrict__ guT,
    const float* __restrict__ sgw, const float* __restrict__ suw,
    float* __restrict__ hid, float* __restrict__ sh)
{
    const int bid = blockIdx.x;
    const float *B1, *B2;
    float* C; int ldc, z = 0, bm, bn;
    if (EXPERT) {
        z = bid >> 8; int rem = bid & 255; bm = rem >> 3; bn = rem & 7;
        if (bm * BM >= d_cnt[z]) return;
        B1 = guT + (long long)z * 2 * HDIM * CDIM + (long long)(bn * 64) * CDIM;
        B2 = B1 + (long long)HDIM * CDIM;
        C  = hid + (long long)z * NTOK * HDIM;
        ldc = HDIM;
    } else {
        bm = bid >> 5; bn = bid & 31;
        B1 = sgw + (long long)(bn * 64) * CDIM;
        B2 = suw + (long long)(bn * 64) * CDIM;
        C  = sh;
        ldc = HSDIM;
    }
    const int K = CDIM;

    extern __shared__ __align__(16) float smem[];
    float* sA = smem;                   // [2][128][AST]
    float* sB = smem + 2 * STG;         // [2][128][AST]  rows 0-63 gate, 64-127 up

    const int tid = threadIdx.x, lane = tid & 31, w = tid >> 5;
    const int ly = lane >> 2, lx = lane & 3;
    const int wm = w >> 1, wn = w & 1;  // 2 x 2 warps

    const float* aPtr[8];
    const float* bPtr[8];
    const int rbase = tid >> 3, kc = (tid & 7) * 4;
#pragma unroll
    for (int c = 0; c < 8; c++) {
        int row = rbase + 16 * c;
        long long arow = EXPERT ? (long long)d_tok[z][bm * BM + row] : (long long)(bm * BM + row);
        aPtr[c] = xr + arow * K;
        bPtr[c] = ((row < 64) ? (B1 + (long long)row * K) : (B2 + (long long)(row - 64) * K));
    }
    auto loadStage = [&](int st, int k0) {
        float* dA = sA + st * STG;
        float* dB = sB + st * STG;
#pragma unroll
        for (int c = 0; c < 8; c++) {
            int row = rbase + 16 * c;
            cp16(dA + row * AST + kc, aPtr[c] + k0 + kc);
            cp16(dB + row * AST + kc, bPtr[c] + k0 + kc);
        }
        asm volatile("cp.async.commit_group;");
    };

    float accG[4][4][4], accU[4][4][4];
#pragma unroll
    for (int a = 0; a < 4; a++)
#pragma unroll
        for (int b = 0; b < 4; b++)
#pragma unroll
            for (int q = 0; q < 4; q++) { accG[a][b][q] = 0.f; accU[a][b][q] = 0.f; }

    const int nk = K / BK;
    loadStage(0, 0);

    for (int kt = 0; kt < nk; kt++) {
        const int st = kt & 1;
        asm volatile("cp.async.wait_group 0;");
        __syncthreads();
        if (kt + 1 < nk) loadStage((kt + 1) & 1, (kt + 1) * BK);

        const float* cA = sA + st * STG;
        const float* cB = sB + st * STG;
#pragma unroll
        for (int ks = 0; ks < 4; ks++) {
            const int kb = ks * 8;
            uint32_t af[4][4], bg[4][2], bu[4][2];
#pragma unroll
            for (int im = 0; im < 4; im++) {
                int r = wm * 64 + im * 16;
                float2 v0 = *(const float2*)(cA + (r     + ly) * AST + kb + 2 * lx);
                float2 v1 = *(const float2*)(cA + (r + 8 + ly) * AST + kb + 2 * lx);
                af[im][0] = __float_as_uint(v0.x); af[im][2] = __float_as_uint(v0.y);
                af[im][1] = __float_as_uint(v1.x); af[im][3] = __float_as_uint(v1.y);
            }
#pragma unroll
            for (int in = 0; in < 4; in++) {
                int cn = wn * 32 + in * 8 + ly;
                float2 g = *(const float2*)(cB + cn * AST + kb + 2 * lx);
                float2 u = *(const float2*)(cB + (64 + cn) * AST + kb + 2 * lx);
                bg[in][0] = __float_as_uint(g.x); bg[in][1] = __float_as_uint(g.y);
                bu[in][0] = __float_as_uint(u.x); bu[in][1] = __float_as_uint(u.y);
            }
#pragma unroll
            for (int im = 0; im < 4; im++)
#pragma unroll
                for (int in = 0; in < 4; in++) {
                    mma8(accG[im][in], af[im], bg[in]);
                    mma8(accU[im][in], af[im], bu[in]);
                }
        }
    }

    // epilogue: out = rna(silu(g)*u), k-paired layout
    const int off0 = pk8(2 * lx);
#pragma unroll
    for (int im = 0; im < 4; im++) {
        int rr = bm * BM + wm * 64 + im * 16 + ly;
#pragma unroll
        for (int in = 0; in < 4; in++) {
            long long base = (long long)rr * ldc + bn * 64 + wn * 32 + in * 8;
            float* g = accG[im][in];
            float* u = accU[im][in];
            C[base + off0]                 = tf32r(silu_f(g[0]) * u[0]);
            C[base + off0 + 2]             = tf32r(silu_f(g[1]) * u[1]);
            C[base + 8LL * ldc + off0]     = tf32r(silu_f(g[2]) * u[2]);
            C[base + 8LL * ldc + off0 + 2] = tf32r(silu_f(g[3]) * u[3]);
        }
    }
}

// ---------------- phase 2: down GEMMs (templated expert/shared) ------------------
// CTA: 128 threads (2x2 warps). Tile: 128 x 128. Warp: 64 x 64.
template <bool EXPERT>
__global__ __launch_bounds__(128) void phase2_kernel(
    const float* __restrict__ hid, const float* __restrict__ dwT,
    const float* __restrict__ sh,  const float* __restrict__ sdw,
    float* __restrict__ pair, float* __restrict__ out)
{
    const int bid = blockIdx.x;
    const float *A, *B; const float* gate; float* C;
    int K, z = 0, bm, bn;
    if (EXPERT) {
        z = bid >> 8; int rem = bid & 255; bm = rem >> 3; bn = rem & 7;
        if (bm * BM >= d_cnt[z]) return;
        A = hid + (long long)z * NTOK * HDIM;
        K = HDIM;
        B = dwT + (long long)z * CDIM * HDIM + (long long)(bn * 128) * HDIM;
        C = pair + (long long)z * NTOK * CDIM;
        gate = d_gate[z];
    } else {
        bm = bid >> 3; bn = bid & 7;
        A = sh; K = HSDIM;
        B = sdw + (long long)(bn * 128) * HSDIM;
        C = out;
        gate = nullptr;
    }

    extern __shared__ __align__(16) float smem[];
    float* sA = smem;                   // [2][128][AST]
    float* sB = smem + 2 * STG;         // [2][128][AST]

    const int tid = threadIdx.x, lane = tid & 31, w = tid >> 5;
    const int ly = lane >> 2, lx = lane & 3;
    const int wm = w >> 1, wn = w & 1;  // 2 x 2 warps, each 64x64

    const int rbase = tid >> 3, kc = (tid & 7) * 4;
    const float* aBase = A + (long long)(bm * BM + rbase) * K;
    const float* bBase = B + (long long)rbase * K;

    auto loadStage = [&](int st, int k0) {
        float* dA = sA + st * STG;
        float* dB = sB + st * STG;
#pragma unroll
        for (int c = 0; c < 8; c++) {
            int row = rbase + 16 * c;
            cp16(dA + row * AST + kc, aBase + (long long)(16 * c) * K + k0 + kc);
            cp16(dB + row * AST + kc, bBase + (long long)(16 * c) * K + k0 + kc);
        }
        asm volatile("cp.async.commit_group;");
    };

    float acc[4][8][4];
#pragma unroll
    for (int a = 0; a < 4; a++)
#pragma unroll
        for (int b = 0; b < 8; b++)
#pragma unroll
            for (int q = 0; q < 4; q++) acc[a][b][q] = 0.f;

    const int nk = K / BK;
    loadStage(0, 0);

    for (int kt = 0; kt < nk; kt++) {
        const int st = kt & 1;
        asm volatile("cp.async.wait_group 0;");
        __syncthreads();
        if (kt + 1 < nk) loadStage((kt + 1) & 1, (kt + 1) * BK);

        const float* cA = sA + st * STG;
        const float* cB = sB + st * STG;
#pragma unroll
        for (int ks = 0; ks < 4; ks++) {
            const int kb = ks * 8;
            uint32_t af[4][4], bf[8][2];
#pragma unroll
            for (int im = 0; im < 4; im++) {
                int r = wm * 64 + im * 16;
                float2 v0 = *(const float2*)(cA + (r     + ly) * AST + kb + 2 * lx);
                float2 v1 = *(const float2*)(cA + (r + 8 + ly) * AST + kb + 2 * lx);
                af[im][0] = __float_as_uint(v0.x); af[im][2] = __float_as_uint(v0.y);
                af[im][1] = __float_as_uint(v1.x); af[im][3] = __float_as_uint(v1.y);
            }
#pragma unroll
            for (int in = 0; in < 8; in++) {
                int cn = wn * 64 + in * 8 + ly;
                float2 bb = *(const float2*)(cB + cn * AST + kb + 2 * lx);
                bf[in][0] = __float_as_uint(bb.x); bf[in][1] = __float_as_uint(bb.y);
            }
#pragma unroll
            for (int im = 0; im < 4; im++)
#pragma unroll
                for (int in = 0; in < 8; in++)
                    mma8(acc[im][in], af[im], bf[in]);
        }
    }

    // epilogue (canonical layout, float2 stores)
#pragma unroll
    for (int im = 0; im < 4; im++) {
        int rr = bm * BM + wm * 64 + im * 16 + ly;
        float s0 = gate ? gate[rr] : 1.f;
        float s1 = gate ? gate[rr + 8] : 1.f;
#pragma unroll
        for (int in = 0; in < 8; in++) {
            long long base = (long long)rr * CDIM + bn * 128 + wn * 64 + in * 8 + lx * 2;
            *(float2*)(C + base)              = make_float2(acc[im][in][0] * s0, acc[im][in][1] * s0);
            *(float2*)(C + base + 8LL * CDIM) = make_float2(acc[im][in][2] * s1, acc[im][in][3] * s1);
        }
    }
}

// ---------------- final combine: out += gated expert pair ----------------
__global__ void combine_kernel(float* __restrict__ out) {
    long long i = (long long)blockIdx.x * 256 + threadIdx.x;
    int t = (int)(i >> 8), j = (int)(i & 255);
    int es0 = d_eslot[t][0], es1 = d_eslot[t][1];
    float4 o  = ((float4*)out)[i];
    float4 p0 = ((const float4*)d_pair)[(long long)es0 * 256 + j];
    float4 p1 = ((const float4*)d_pair)[(long long)es1 * 256 + j];
    o.x += p0.x + p1.x; o.y += p0.y + p1.y;
    o.z += p0.z + p1.z; o.w += p0.w + p1.w;
    ((float4*)out)[i] = o;
}

// ---------------- launch (round-10 DAG) ----------------
extern "C" void kernel_launch(void* const* d_in, const int* in_sizes, int n_in,
                              void* d_out, int out_size) {
    const float* x   = (const float*)d_in[0];
    const float* rw  = (const float*)d_in[1];
    const float* guw = (const float*)d_in[2];
    const float* dw  = (const float*)d_in[3];
    const float* sgw = (const float*)d_in[4];
    const float* suw = (const float*)d_in[5];
    const float* sdw = (const float*)d_in[6];
    float* out = (float*)d_out;

    void* a;
    float *p_hid, *p_pair, *p_sh, *p_xr, *p_guT, *p_dwT, *p_sgwr, *p_suwr, *p_sdwr;
    cudaGetSymbolAddress(&a, d_hid);  p_hid  = (float*)a;
    cudaGetSymbolAddress(&a, d_pair); p_pair = (float*)a;
    cudaGetSymbolAddress(&a, d_sh);   p_sh   = (float*)a;
    cudaGetSymbolAddress(&a, d_xr);   p_xr   = (float*)a;
    cudaGetSymbolAddress(&a, d_guT);  p_guT  = (float*)a;
    cudaGetSymbolAddress(&a, d_dwT);  p_dwT  = (float*)a;
    cudaGetSymbolAddress(&a, d_sgwr); p_sgwr = (float*)a;
    cudaGetSymbolAddress(&a, d_suwr); p_suwr = (float*)a;
    cudaGetSymbolAddress(&a, d_sdwr); p_sdwr = (float*)a;
    void* cntAddr; cudaGetSymbolAddress(&cntAddr, d_cnt);

    static cudaStream_t s1 = nullptr, s2 = nullptr;
    static cudaEvent_t ev0 = nullptr, evG = nullptr, evD = nullptr, evP = nullptr,
                       evR = nullptr, evS = nullptr;
    if (!s1) {
        cudaStreamCreateWithFlags(&s1, cudaStreamNonBlocking);
        cudaStreamCreateWithFlags(&s2, cudaStreamNonBlocking);
        cudaEventCreateWithFlags(&ev0, cudaEventDisableTiming);
        cudaEventCreateWithFlags(&evG, cudaEventDisableTiming);
        cudaEventCreateWithFlags(&evD, cudaEventDisableTiming);
        cudaEventCreateWithFlags(&evP, cudaEventDisableTiming);
        cudaEventCreateWithFlags(&evR, cudaEventDisableTiming);
        cudaEventCreateWithFlags(&evS, cudaEventDisableTiming);
        cudaFuncSetAttribute(phase1_kernel<true >, cudaFuncAttributeMaxDynamicSharedMemorySize, SMEMB);
        cudaFuncSetAttribute(phase1_kernel<false>, cudaFuncAttributeMaxDynamicSharedMemorySize, SMEMB);
        cudaFuncSetAttribute(phase2_kernel<true >, cudaFuncAttributeMaxDynamicSharedMemorySize, SMEMB);
        cudaFuncSetAttribute(phase2_kernel<false>, cudaFuncAttributeMaxDynamicSharedMemorySize, SMEMB);
    }

    // ---- fork point ----
    cudaEventRecord(ev0, 0);
    cudaStreamWaitEvent(s1, ev0, 0);

    // side stream s1: weight preprocessing (independent of router)
    transpose_rna_perm<<<dim3(2 * HDIM / 32, CDIM / 32, ENUM), dim3(32, 8), 0, s1>>>(guw, p_guT, CDIM, 2 * HDIM);
    cudaEventRecord(evG, s1);
    transpose_rna_perm<<<dim3(CDIM / 32, HDIM / 32, ENUM), dim3(32, 8), 0, s1>>>(dw, p_dwT, HDIM, CDIM);
    cudaEventRecord(evD, s1);
    round_perm3<<<dim3(HSDIM * CDIM / 8 / 256, 3), 256, 0, s1>>>(sgw, p_sgwr, suw, p_suwr, sdw, p_sdwr);
    cudaEventRecord(evP, s1);

    // main stream: vectorized router (emits k-paired tf32 x + routing tables)
    cudaMemsetAsync(cntAddr, 0, sizeof(int) * ENUM, 0);
    router_kernel<<<NTOK / 8, 256, 0, 0>>>(x, rw, p_xr);
    cudaEventRecord(evR, 0);

    // expert chain on main stream: p1e -> p2e
    cudaStreamWaitEvent(0, evG, 0);
    phase1_kernel<true><<<2048, 128, SMEMB, 0>>>(p_xr, p_guT, p_sgwr, p_suwr, p_hid, p_sh);
    cudaStreamWaitEvent(0, evD, 0);
    phase2_kernel<true><<<2048, 128, SMEMB, 0>>>(p_hid, p_dwT, p_sh, p_sdwr, p_pair, out);

    // shared chain on s2: p1s -> p2s (writes out base)
    cudaStreamWaitEvent(s2, evR, 0);
    cudaStreamWaitEvent(s2, evP, 0);
    phase1_kernel<false><<<1024, 128, SMEMB, s2>>>(p_xr, p_guT, p_sgwr, p_suwr, p_hid, p_sh);
    phase2_kernel<false><<<256, 128, SMEMB, s2>>>(p_hid, p_dwT, p_sh, p_sdwr, p_pair, out);
    cudaEventRecord(evS, s2);

    // ---- join: combine after both chains ----
    cudaStreamWaitEvent(0, evS, 0);
    combine_kernel<<<NTOK * CDIM / 4 / 256, 256, 0, 0>>>(out);

    (void)in_sizes; (void)n_in; (void)out_size;
}

// round 13
// speedup vs baseline: 1.7480x; 1.7049x over previous
#include <cuda_runtime.h>
#include <cuda_fp16.h>
#include <cstdint>

// ---------------- problem dims ----------------
#define NTOK 4096
#define CDIM 1024
#define ENUM 8
#define HDIM 512
#define HSDIM 2048

// ---------------- GEMM tiling (fp16 m16n8k16) ----------------
#define BM 128
#define BKH 64                        // k per tile (halves)
#define AST2 80                       // smem row stride in halves (160B) -> conflict-free LDS.64
#define STGH (BM * AST2)              // 10240 halves = 20480 B per operand stage
#define SMEMB (4 * STGH * 2)          // 81920 B (2 stages x (A+B))

// fp16 k-permutation within each 16-wide k-group:
// storage order [0,1,8,9, 2,3,10,11, 4,5,12,13, 6,7,14,15]
// pos(c) = ((c&7)>>1)*4 + ((c>>3)&1)*2 + (c&1)
__device__ __forceinline__ int ph16(int c) {
    return (((c & 7) >> 1) << 2) | (((c >> 3) & 1) << 1) | (c & 1);
}

// ---------------- device scratch ----------------
__device__ int    d_cnt[ENUM];
__device__ int    d_tok[ENUM][NTOK];
__device__ float  d_gate[ENUM][NTOK];
__device__ int    d_eslot[NTOK][2];
__device__ __half d_hid [ENUM*NTOK*HDIM];    // fp16 perm hidden
__device__ float  d_pair[ENUM*NTOK*CDIM];    // gate-scaled expert out (fp32 canonical)
__device__ __half d_sh  [NTOK*HSDIM];        // fp16 perm shared hidden
__device__ __half d_xr  [NTOK*CDIM];         // fp16 perm x
__device__ __half d_guT [ENUM*2*HDIM*CDIM];  // [E][2H][C] transposed, fp16 perm
__device__ __half d_dwT [ENUM*CDIM*HDIM];    // [E][C][H] transposed, fp16 perm
__device__ __half d_sgwr[HSDIM*CDIM];        // fp16 perm
__device__ __half d_suwr[HSDIM*CDIM];        // fp16 perm
__device__ __half d_sdwr[CDIM*HSDIM];        // fp16 perm

// ---------------- helpers ----------------
__device__ __forceinline__ void cp16(__half* s, const __half* g) {
    uint32_t sa = (uint32_t)__cvta_generic_to_shared(s);
    asm volatile("cp.async.cg.shared.global [%0], [%1], 16;" :: "r"(sa), "l"(g));
}
__device__ __forceinline__ void mma16(float* d, const uint32_t* a, const uint32_t* b) {
    asm volatile(
        "mma.sync.aligned.m16n8k16.row.col.f32.f16.f16.f32 "
        "{%0,%1,%2,%3},{%4,%5,%6,%7},{%8,%9},{%0,%1,%2,%3};"
        : "+f"(d[0]), "+f"(d[1]), "+f"(d[2]), "+f"(d[3])
        : "r"(a[0]), "r"(a[1]), "r"(a[2]), "r"(a[3]), "r"(b[0]), "r"(b[1]));
}
__device__ __forceinline__ float silu_f(float v) { return v / (1.f + expf(-v)); }
__device__ __forceinline__ uint32_t h2u(float a, float b) {
    __half2 h = __floats2half2_rn(a, b);
    return *(uint32_t*)&h;
}

// ---------------- router: logits/top2/gates + fused fp16-perm xr ----------------
__global__ void router_kernel(const float* __restrict__ x, const float* __restrict__ rw,
                              __half* __restrict__ xw) {
    int t = blockIdx.x * (blockDim.x >> 5) + (threadIdx.x >> 5);
    int lane = threadIdx.x & 31;
    if (t >= NTOK) return;
    const float4* xr4 = (const float4*)(x + (long long)t * CDIM);
    uint4* xo = (uint4*)(xw + (long long)t * CDIM);   // 2 uint4 per 16-group
    float acc[ENUM];
#pragma unroll
    for (int e = 0; e < ENUM; e++) acc[e] = 0.f;
#pragma unroll
    for (int g = lane; g < CDIM / 16; g += 32) {       // 2 iterations
        float4 v0 = xr4[4 * g], v1 = xr4[4 * g + 1], v2 = xr4[4 * g + 2], v3 = xr4[4 * g + 3];
#pragma unroll
        for (int e = 0; e < ENUM; e++) {
            const float4* w4 = (const float4*)(rw + e * CDIM);
            float4 w0 = w4[4 * g], w1 = w4[4 * g + 1], w2 = w4[4 * g + 2], w3 = w4[4 * g + 3];
            acc[e] += v0.x * w0.x + v0.y * w0.y + v0.z * w0.z + v0.w * w0.w
                    + v1.x * w1.x + v1.y * w1.y + v1.z * w1.z + v1.w * w1.w
                    + v2.x * w2.x + v2.y * w2.y + v2.z * w2.z + v2.w * w2.w
                    + v3.x * w3.x + v3.y * w3.y + v3.z * w3.z + v3.w * w3.w;
        }
        // perm fp16 store: [c0c1, c8c9, c2c3, c10c11 | c4c5, c12c13, c6c7, c14c15]
        uint4 o0, o1;
        o0.x = h2u(v0.x, v0.y); o0.y = h2u(v2.x, v2.y);
        o0.z = h2u(v0.z, v0.w); o0.w = h2u(v2.z, v2.w);
        o1.x = h2u(v1.x, v1.y); o1.y = h2u(v3.x, v3.y);
        o1.z = h2u(v1.z, v1.w); o1.w = h2u(v3.z, v3.w);
        xo[2 * g] = o0; xo[2 * g + 1] = o1;
    }
#pragma unroll
    for (int e = 0; e < ENUM; e++)
#pragma unroll
        for (int off = 16; off; off >>= 1) acc[e] += __shfl_xor_sync(~0u, acc[e], off);
    if (lane == 0) {
        int i0 = 0; float v0 = acc[0];
#pragma unroll
        for (int e = 1; e < ENUM; e++) if (acc[e] > v0) { v0 = acc[e]; i0 = e; }
        int i1 = -1; float v1 = -3.0e38f;
#pragma unroll
        for (int e = 0; e < ENUM; e++) if (e != i0 && acc[e] > v1) { v1 = acc[e]; i1 = e; }
        float g0 = 1.f / (1.f + expf(-v0));
        float g1 = 1.f / (1.f + expf(-v1));
        int s0 = atomicAdd(&d_cnt[i0], 1);
        int s1 = atomicAdd(&d_cnt[i1], 1);
        d_tok[i0][s0] = t; d_gate[i0][s0] = g0; d_eslot[t][0] = i0 * NTOK + s0;
        d_tok[i1][s1] = t; d_gate[i1][s1] = g1; d_eslot[t][1] = i1 * NTOK + s1;
    }
}

// ---------------- preprocessing ----------------
// 3 shared-weight arrays fp32 [N,K] -> fp16 perm (one 16-group per thread)
__global__ void round_perm3(const float* __restrict__ s0, __half* __restrict__ d0,
                            const float* __restrict__ s1, __half* __restrict__ d1,
                            const float* __restrict__ s2, __half* __restrict__ d2) {
    const float* src = (blockIdx.y == 0) ? s0 : (blockIdx.y == 1) ? s1 : s2;
    __half*      dst = (blockIdx.y == 0) ? d0 : (blockIdx.y == 1) ? d1 : d2;
    long long g = (long long)blockIdx.x * 256 + threadIdx.x;
    const float4* s4 = (const float4*)src;
    float4 v0 = s4[4 * g], v1 = s4[4 * g + 1], v2 = s4[4 * g + 2], v3 = s4[4 * g + 3];
    uint4 o0, o1;
    o0.x = h2u(v0.x, v0.y); o0.y = h2u(v2.x, v2.y);
    o0.z = h2u(v0.z, v0.w); o0.w = h2u(v2.z, v2.w);
    o1.x = h2u(v1.x, v1.y); o1.y = h2u(v3.x, v3.y);
    o1.z = h2u(v1.z, v1.w); o1.w = h2u(v3.z, v3.w);
    ((uint4*)dst)[2 * g] = o0; ((uint4*)dst)[2 * g + 1] = o1;
}
// dst[z][c][perm16(r)] = h(src[z][r][c])
__global__ void transpose_h_perm(const float* __restrict__ src, __half* __restrict__ dst,
                                 int R, int C) {
    __shared__ float tile[32][33];
    long long zi = (long long)blockIdx.z * R * C;
    long long zo = zi;
    int r0 = blockIdx.y * 32, c0 = blockIdx.x * 32;
    int tx = threadIdx.x, ty = threadIdx.y;
#pragma unroll
    for (int i = 0; i < 32; i += 8)
        tile[ty + i][tx] = src[zi + (long long)(r0 + ty + i) * C + c0 + tx];
    __syncthreads();
    int rp = r0 + (tx & 16) + ph16(tx & 15);
#pragma unroll
    for (int i = 0; i < 32; i += 8)
        dst[zo + (long long)(c0 + ty + i) * R + rp] = __float2half_rn(tile[tx][ty + i]);
}

// ---------------- phase 1: fused SwiGLU GEMMs (fp16, templated expert/shared) ---
// CTA: 128 threads (2x2 warps). Tile: 128 rows x 64 hidden cols.
template <bool EXPERT>
__global__ __launch_bounds__(128) void phase1_kernel(
    const __half* __restrict__ xr, const __half* __restrict__ guT,
    const __half* __restrict__ sgw, const __half* __restrict__ suw,
    __half* __restrict__ hid, __half* __restrict__ sh)
{
    const int bid = blockIdx.x;
    const __half *B1, *B2;
    __half* C; int ldc, z = 0, bm, bn;
    if (EXPERT) {
        z = bid >> 8; int rem = bid & 255; bm = rem >> 3; bn = rem & 7;
        if (bm * BM >= d_cnt[z]) return;
        B1 = guT + (long long)z * 2 * HDIM * CDIM + (long long)(bn * 64) * CDIM;
        B2 = B1 + (long long)HDIM * CDIM;
        C  = hid + (long long)z * NTOK * HDIM;
        ldc = HDIM;
    } else {
        bm = bid >> 5; bn = bid & 31;
        B1 = sgw + (long long)(bn * 64) * CDIM;
        B2 = suw + (long long)(bn * 64) * CDIM;
        C  = sh;
        ldc = HSDIM;
    }
    const int K = CDIM;

    extern __shared__ __align__(16) __half smem[];
    __half* sA = smem;                  // [2][128][AST2]
    __half* sB = smem + 2 * STGH;       // [2][128][AST2]  rows 0-63 gate, 64-127 up

    const int tid = threadIdx.x, lane = tid & 31, w = tid >> 5;
    const int ly = lane >> 2, lx = lane & 3;
    const int wm = w >> 1, wn = w & 1;  // 2 x 2 warps

    const __half* aPtr[8];
    const __half* bPtr[8];
    const int rbase = tid >> 3, kc = (tid & 7) * 8;   // halves
#pragma unroll
    for (int c = 0; c < 8; c++) {
        int row = rbase + 16 * c;
        long long arow = EXPERT ? (long long)d_tok[z][bm * BM + row] : (long long)(bm * BM + row);
        aPtr[c] = xr + arow * K;
        bPtr[c] = ((row < 64) ? (B1 + (long long)row * K) : (B2 + (long long)(row - 64) * K));
    }
    auto loadStage = [&](int st, int k0) {
        __half* dA = sA + st * STGH;
        __half* dB = sB + st * STGH;
#pragma unroll
        for (int c = 0; c < 8; c++) {
            int row = rbase + 16 * c;
            cp16(dA + row * AST2 + kc, aPtr[c] + k0 + kc);
            cp16(dB + row * AST2 + kc, bPtr[c] + k0 + kc);
        }
        asm volatile("cp.async.commit_group;");
    };

    float accG[4][4][4], accU[4][4][4];
#pragma unroll
    for (int a = 0; a < 4; a++)
#pragma unroll
        for (int b = 0; b < 4; b++)
#pragma unroll
            for (int q = 0; q < 4; q++) { accG[a][b][q] = 0.f; accU[a][b][q] = 0.f; }

    const int nk = K / BKH;
    loadStage(0, 0);

    for (int kt = 0; kt < nk; kt++) {
        const int st = kt & 1;
        asm volatile("cp.async.wait_group 0;");
        __syncthreads();
        if (kt + 1 < nk) loadStage((kt + 1) & 1, (kt + 1) * BKH);

        const __half* cA = sA + st * STGH;
        const __half* cB = sB + st * STGH;
#pragma unroll
        for (int kg = 0; kg < 4; kg++) {
            const int kb = kg * 16 + lx * 4;
            uint32_t af[4][4], bg[4][2], bu[4][2];
#pragma unroll
            for (int im = 0; im < 4; im++) {
                int r = wm * 64 + im * 16;
                uint2 v0 = *(const uint2*)(cA + (r     + ly) * AST2 + kb);
                uint2 v1 = *(const uint2*)(cA + (r + 8 + ly) * AST2 + kb);
                af[im][0] = v0.x; af[im][1] = v1.x; af[im][2] = v0.y; af[im][3] = v1.y;
            }
#pragma unroll
            for (int in = 0; in < 4; in++) {
                int cn = wn * 32 + in * 8 + ly;
                uint2 g = *(const uint2*)(cB + cn * AST2 + kb);
                uint2 u = *(const uint2*)(cB + (64 + cn) * AST2 + kb);
                bg[in][0] = g.x; bg[in][1] = g.y;
                bu[in][0] = u.x; bu[in][1] = u.y;
            }
#pragma unroll
            for (int im = 0; im < 4; im++)
#pragma unroll
                for (int in = 0; in < 4; in++) {
                    mma16(accG[im][in], af[im], bg[in]);
                    mma16(accU[im][in], af[im], bu[in]);
                }
        }
    }

    // epilogue: out = fp16(silu(g)*u), stored in perm16 layout (phase2 operand)
#pragma unroll
    for (int im = 0; im < 4; im++) {
        int rr = bm * BM + wm * 64 + im * 16 + ly;
#pragma unroll
        for (int in = 0; in < 4; in++) {
            int G   = wn * 2 + (in >> 1);              // 16-group within the 64-col tile
            int pos = lx * 4 + (in & 1) * 2;
            long long off = (long long)rr * ldc + bn * 64 + G * 16 + pos;
            float* g = accG[im][in];
            float* u = accU[im][in];
            *(uint32_t*)(C + off)            = h2u(silu_f(g[0]) * u[0], silu_f(g[1]) * u[1]);
            *(uint32_t*)(C + off + 8LL * ldc)= h2u(silu_f(g[2]) * u[2], silu_f(g[3]) * u[3]);
        }
    }
}

// ---------------- phase 2: down GEMMs (fp16, templated expert/shared) ------------
// CTA: 128 threads (2x2 warps). Tile: 128 x 128. Warp: 64 x 64.
template <bool EXPERT>
__global__ __launch_bounds__(128) void phase2_kernel(
    const __half* __restrict__ hid, const __half* __restrict__ dwT,
    const __half* __restrict__ sh,  const __half* __restrict__ sdw,
    float* __restrict__ pair, float* __restrict__ out)
{
    const int bid = blockIdx.x;
    const __half *A, *B; const float* gate; float* C;
    int K, z = 0, bm, bn;
    if (EXPERT) {
        z = bid >> 8; int rem = bid & 255; bm = rem >> 3; bn = rem & 7;
        if (bm * BM >= d_cnt[z]) return;
        A = hid + (long long)z * NTOK * HDIM;
        K = HDIM;
        B = dwT + (long long)z * CDIM * HDIM + (long long)(bn * 128) * HDIM;
        C = pair + (long long)z * NTOK * CDIM;
        gate = d_gate[z];
    } else {
        bm = bid >> 3; bn = bid & 7;
        A = sh; K = HSDIM;
        B = sdw + (long long)(bn * 128) * HSDIM;
        C = out;
        gate = nullptr;
    }

    extern __shared__ __align__(16) __half smem[];
    __half* sA = smem;                  // [2][128][AST2]
    __half* sB = smem + 2 * STGH;       // [2][128][AST2]

    const int tid = threadIdx.x, lane = tid & 31, w = tid >> 5;
    const int ly = lane >> 2, lx = lane & 3;
    const int wm = w >> 1, wn = w & 1;  // 2 x 2 warps, each 64x64

    const int rbase = tid >> 3, kc = (tid & 7) * 8;
    const __half* aBase = A + (long long)(bm * BM + rbase) * K;
    const __half* bBase = B + (long long)rbase * K;

    auto loadStage = [&](int st, int k0) {
        __half* dA = sA + st * STGH;
        __half* dB = sB + st * STGH;
#pragma unroll
        for (int c = 0; c < 8; c++) {
            int row = rbase + 16 * c;
            cp16(dA + row * AST2 + kc, aBase + (long long)(16 * c) * K + k0 + kc);
            cp16(dB + row * AST2 + kc, bBase + (long long)(16 * c) * K + k0 + kc);
        }
        asm volatile("cp.async.commit_group;");
    };

    float acc[4][8][4];
#pragma unroll
    for (int a = 0; a < 4; a++)
#pragma unroll
        for (int b = 0; b < 8; b++)
#pragma unroll
            for (int q = 0; q < 4; q++) acc[a][b][q] = 0.f;

    const int nk = K / BKH;
    loadStage(0, 0);

    for (int kt = 0; kt < nk; kt++) {
        const int st = kt & 1;
        asm volatile("cp.async.wait_group 0;");
        __syncthreads();
        if (kt + 1 < nk) loadStage((kt + 1) & 1, (kt + 1) * BKH);

        const __half* cA = sA + st * STGH;
        const __half* cB = sB + st * STGH;
#pragma unroll
        for (int kg = 0; kg < 4; kg++) {
            const int kb = kg * 16 + lx * 4;
            uint32_t af[4][4], bf[8][2];
#pragma unroll
            for (int im = 0; im < 4; im++) {
                int r = wm * 64 + im * 16;
                uint2 v0 = *(const uint2*)(cA + (r     + ly) * AST2 + kb);
                uint2 v1 = *(const uint2*)(cA + (r + 8 + ly) * AST2 + kb);
                af[im][0] = v0.x; af[im][1] = v1.x; af[im][2] = v0.y; af[im][3] = v1.y;
            }
#pragma unroll
            for (int in = 0; in < 8; in++) {
                int cn = wn * 64 + in * 8 + ly;
                uint2 bb = *(const uint2*)(cB + cn * AST2 + kb);
                bf[in][0] = bb.x; bf[in][1] = bb.y;
            }
#pragma unroll
            for (int im = 0; im < 4; im++)
#pragma unroll
                for (int in = 0; in < 8; in++)
                    mma16(acc[im][in], af[im], bf[in]);
        }
    }

    // epilogue (fp32 canonical layout, float2 stores)
#pragma unroll
    for (int im = 0; im < 4; im++) {
        int rr = bm * BM + wm * 64 + im * 16 + ly;
        float s0 = gate ? gate[rr] : 1.f;
        float s1 = gate ? gate[rr + 8] : 1.f;
#pragma unroll
        for (int in = 0; in < 8; in++) {
            long long base = (long long)rr * CDIM + bn * 128 + wn * 64 + in * 8 + lx * 2;
            *(float2*)(C + base)              = make_float2(acc[im][in][0] * s0, acc[im][in][1] * s0);
            *(float2*)(C + base + 8LL * CDIM) = make_float2(acc[im][in][2] * s1, acc[im][in][3] * s1);
        }
    }
}

// ---------------- final combine: out += gated expert pair ----------------
__global__ void combine_kernel(float* __restrict__ out) {
    long long i = (long long)blockIdx.x * 256 + threadIdx.x;
    int t = (int)(i >> 8), j = (int)(i & 255);
    int es0 = d_eslot[t][0], es1 = d_eslot[t][1];
    float4 o  = ((float4*)out)[i];
    float4 p0 = ((const float4*)d_pair)[(long long)es0 * 256 + j];
    float4 p1 = ((const float4*)d_pair)[(long long)es1 * 256 + j];
    o.x += p0.x + p1.x; o.y += p0.y + p1.y;
    o.z += p0.z + p1.z; o.w += p0.w + p1.w;
    ((float4*)out)[i] = o;
}

// ---------------- launch (round-10 DAG) ----------------
extern "C" void kernel_launch(void* const* d_in, const int* in_sizes, int n_in,
                              void* d_out, int out_size) {
    const float* x   = (const float*)d_in[0];
    const float* rw  = (const float*)d_in[1];
    const float* guw = (const float*)d_in[2];
    const float* dw  = (const float*)d_in[3];
    const float* sgw = (const float*)d_in[4];
    const float* suw = (const float*)d_in[5];
    const float* sdw = (const float*)d_in[6];
    float* out = (float*)d_out;

    void* a;
    float* p_pair; float* dummy;
    __half *p_hid, *p_sh, *p_xr, *p_guT, *p_dwT, *p_sgwr, *p_suwr, *p_sdwr;
    cudaGetSymbolAddress(&a, d_hid);  p_hid  = (__half*)a;
    cudaGetSymbolAddress(&a, d_pair); p_pair = (float*)a;
    cudaGetSymbolAddress(&a, d_sh);   p_sh   = (__half*)a;
    cudaGetSymbolAddress(&a, d_xr);   p_xr   = (__half*)a;
    cudaGetSymbolAddress(&a, d_guT);  p_guT  = (__half*)a;
    cudaGetSymbolAddress(&a, d_dwT);  p_dwT  = (__half*)a;
    cudaGetSymbolAddress(&a, d_sgwr); p_sgwr = (__half*)a;
    cudaGetSymbolAddress(&a, d_suwr); p_suwr = (__half*)a;
    cudaGetSymbolAddress(&a, d_sdwr); p_sdwr = (__half*)a;
    void* cntAddr; cudaGetSymbolAddress(&cntAddr, d_cnt);
    (void)dummy;

    static cudaStream_t s1 = nullptr, s2 = nullptr;
    static cudaEvent_t ev0 = nullptr, evG = nullptr, evD = nullptr, evP = nullptr,
                       evR = nullptr, evS = nullptr;
    if (!s1) {
        cudaStreamCreateWithFlags(&s1, cudaStreamNonBlocking);
        cudaStreamCreateWithFlags(&s2, cudaStreamNonBlocking);
        cudaEventCreateWithFlags(&ev0, cudaEventDisableTiming);
        cudaEventCreateWithFlags(&evG, cudaEventDisableTiming);
        cudaEventCreateWithFlags(&evD, cudaEventDisableTiming);
        cudaEventCreateWithFlags(&evP, cudaEventDisableTiming);
        cudaEventCreateWithFlags(&evR, cudaEventDisableTiming);
        cudaEventCreateWithFlags(&evS, cudaEventDisableTiming);
        cudaFuncSetAttribute(phase1_kernel<true >, cudaFuncAttributeMaxDynamicSharedMemorySize, SMEMB);
        cudaFuncSetAttribute(phase1_kernel<false>, cudaFuncAttributeMaxDynamicSharedMemorySize, SMEMB);
        cudaFuncSetAttribute(phase2_kernel<true >, cudaFuncAttributeMaxDynamicSharedMemorySize, SMEMB);
        cudaFuncSetAttribute(phase2_kernel<false>, cudaFuncAttributeMaxDynamicSharedMemorySize, SMEMB);
    }

    // ---- fork point ----
    cudaEventRecord(ev0, 0);
    cudaStreamWaitEvent(s1, ev0, 0);

    // side stream s1: weight preprocessing (independent of router)
    transpose_h_perm<<<dim3(2 * HDIM / 32, CDIM / 32, ENUM), dim3(32, 8), 0, s1>>>(guw, p_guT, CDIM, 2 * HDIM);
    cudaEventRecord(evG, s1);
    transpose_h_perm<<<dim3(CDIM / 32, HDIM / 32, ENUM), dim3(32, 8), 0, s1>>>(dw, p_dwT, HDIM, CDIM);
    cudaEventRecord(evD, s1);
    round_perm3<<<dim3(HSDIM * CDIM / 16 / 256, 3), 256, 0, s1>>>(sgw, p_sgwr, suw, p_suwr, sdw, p_sdwr);
    cudaEventRecord(evP, s1);

    // main stream: router (emits fp16-perm x + routing tables)
    cudaMemsetAsync(cntAddr, 0, sizeof(int) * ENUM, 0);
    router_kernel<<<NTOK / 8, 256, 0, 0>>>(x, rw, p_xr);
    cudaEventRecord(evR, 0);

    // expert chain on main stream: p1e -> p2e
    cudaStreamWaitEvent(0, evG, 0);
    phase1_kernel<true><<<2048, 128, SMEMB, 0>>>(p_xr, p_guT, p_sgwr, p_suwr, p_hid, p_sh);
    cudaStreamWaitEvent(0, evD, 0);
    phase2_kernel<true><<<2048, 128, SMEMB, 0>>>(p_hid, p_dwT, p_sh, p_sdwr, p_pair, out);

    // shared chain on s2: p1s -> p2s (writes out base)
    cudaStreamWaitEvent(s2, evR, 0);
    cudaStreamWaitEvent(s2, evP, 0);
    phase1_kernel<false><<<1024, 128, SMEMB, s2>>>(p_xr, p_guT, p_sgwr, p_suwr, p_hid, p_sh);
    phase2_kernel<false><<<256, 128, SMEMB, s2>>>(p_hid, p_dwT, p_sh, p_sdwr, p_pair, out);
    cudaEventRecord(evS, s2);

    // ---- join: combine after both chains ----
    cudaStreamWaitEvent(0, evS, 0);
    combine_kernel<<<NTOK * CDIM / 4 / 256, 256, 0, 0>>>(out);

    (void)in_sizes; (void)n_in; (void)out_size;
}

// round 14
// speedup vs baseline: 1.7998x; 1.0296x over previous
#include <cuda_runtime.h>
#include <cuda_fp16.h>
#include <cstdint>

// ---------------- problem dims ----------------
#define NTOK 4096
#define CDIM 1024
#define ENUM 8
#define HDIM 512
#define HSDIM 2048

// ---------------- GEMM tiling (fp16 m16n8k16) ----------------
#define BM 128
#define BKH 64                        // k per tile (halves)
#define AST2 80                       // smem row stride in halves (160B) -> conflict-free LDS.64
#define STGH (BM * AST2)              // 10240 halves = 20480 B per operand stage
#define SMEMB (4 * STGH * 2)          // 81920 B (2 stages x (A+B))

// fp16 k-permutation within each 16-wide k-group:
// storage order [0,1,8,9, 2,3,10,11, 4,5,12,13, 6,7,14,15]
__device__ __forceinline__ int ph16(int c) {
    return (((c & 7) >> 1) << 2) | (((c >> 3) & 1) << 1) | (c & 1);
}

// ---------------- device scratch ----------------
__device__ int    d_cnt[ENUM];
__device__ int    d_tok[ENUM][NTOK];
__device__ float  d_gate[ENUM][NTOK];
__device__ int    d_eslot[NTOK][2];
__device__ __half d_hid [ENUM*NTOK*HDIM];    // fp16 perm hidden
__device__ float  d_pair[ENUM*NTOK*CDIM];    // gate-scaled expert out (fp32 canonical)
__device__ __half d_sh  [NTOK*HSDIM];        // fp16 perm shared hidden
__device__ __half d_xr  [NTOK*CDIM];         // fp16 perm x
__device__ __half d_guT [ENUM*2*HDIM*CDIM];  // [E][2H][C] transposed, fp16 perm
__device__ __half d_dwT [ENUM*CDIM*HDIM];    // [E][C][H] transposed, fp16 perm
__device__ __half d_sgwr[HSDIM*CDIM];        // fp16 perm
__device__ __half d_suwr[HSDIM*CDIM];        // fp16 perm
__device__ __half d_sdwr[CDIM*HSDIM];        // fp16 perm

// ---------------- helpers ----------------
__device__ __forceinline__ void cp16(__half* s, const __half* g) {
    uint32_t sa = (uint32_t)__cvta_generic_to_shared(s);
    asm volatile("cp.async.cg.shared.global [%0], [%1], 16;" :: "r"(sa), "l"(g));
}
__device__ __forceinline__ void mma16(float* d, const uint32_t* a, const uint32_t* b) {
    asm volatile(
        "mma.sync.aligned.m16n8k16.row.col.f32.f16.f16.f32 "
        "{%0,%1,%2,%3},{%4,%5,%6,%7},{%8,%9},{%0,%1,%2,%3};"
        : "+f"(d[0]), "+f"(d[1]), "+f"(d[2]), "+f"(d[3])
        : "r"(a[0]), "r"(a[1]), "r"(a[2]), "r"(a[3]), "r"(b[0]), "r"(b[1]));
}
__device__ __forceinline__ float silu_f(float v) { return v / (1.f + expf(-v)); }
__device__ __forceinline__ uint32_t h2u(float a, float b) {
    __half2 h = __floats2half2_rn(a, b);
    return *(uint32_t*)&h;
}

// ---------------- router: 2 warps/token, 1 iteration/lane -----------------------
// block = 256 threads = 8 warps = 4 tokens. Warp pair (2w, 2w+1) handles token;
// each warp covers half of CDIM (512 floats = 32 16-groups, one per lane).
__global__ void router_kernel(const float* __restrict__ x, const float* __restrict__ rw,
                              __half* __restrict__ xw) {
    __shared__ float part[4][2][ENUM];
    const int wid = threadIdx.x >> 5, lane = threadIdx.x & 31;
    const int tl = wid >> 1, half = wid & 1;
    const int t = blockIdx.x * 4 + tl;
    const long long base = (long long)t * CDIM + half * (CDIM / 2);

    const float4* x4 = (const float4*)(x + base);
    float4 v0 = x4[lane * 4], v1 = x4[lane * 4 + 1], v2 = x4[lane * 4 + 2], v3 = x4[lane * 4 + 3];

    float acc[ENUM];
#pragma unroll
    for (int e = 0; e < ENUM; e++) {
        const float4* w4 = (const float4*)(rw + e * CDIM + half * (CDIM / 2));
        float4 w0 = w4[lane * 4], w1 = w4[lane * 4 + 1], w2 = w4[lane * 4 + 2], w3 = w4[lane * 4 + 3];
        acc[e] = v0.x * w0.x + v0.y * w0.y + v0.z * w0.z + v0.w * w0.w
               + v1.x * w1.x + v1.y * w1.y + v1.z * w1.z + v1.w * w1.w
               + v2.x * w2.x + v2.y * w2.y + v2.z * w2.z + v2.w * w2.w
               + v3.x * w3.x + v3.y * w3.y + v3.z * w3.z + v3.w * w3.w;
    }

    // fp16 perm store of this lane's 16-group
    uint4 o0, o1;
    o0.x = h2u(v0.x, v0.y); o0.y = h2u(v2.x, v2.y);
    o0.z = h2u(v0.z, v0.w); o0.w = h2u(v2.z, v2.w);
    o1.x = h2u(v1.x, v1.y); o1.y = h2u(v3.x, v3.y);
    o1.z = h2u(v1.z, v1.w); o1.w = h2u(v3.z, v3.w);
    uint4* xo = (uint4*)(xw + base);
    xo[lane * 2] = o0; xo[lane * 2 + 1] = o1;

#pragma unroll
    for (int e = 0; e < ENUM; e++)
#pragma unroll
        for (int off = 16; off; off >>= 1) acc[e] += __shfl_xor_sync(~0u, acc[e], off);
    if (lane < ENUM) part[tl][half][lane] = acc[lane];   // lane e holds... no: all lanes hold the sum
    __syncthreads();

    if (half == 0 && lane == 0) {
        float lg[ENUM];
#pragma unroll
        for (int e = 0; e < ENUM; e++) lg[e] = part[tl][0][e] + part[tl][1][e];
        int i0 = 0; float v0m = lg[0];
#pragma unroll
        for (int e = 1; e < ENUM; e++) if (lg[e] > v0m) { v0m = lg[e]; i0 = e; }
        int i1 = -1; float v1m = -3.0e38f;
#pragma unroll
        for (int e = 0; e < ENUM; e++) if (e != i0 && lg[e] > v1m) { v1m = lg[e]; i1 = e; }
        float g0 = 1.f / (1.f + expf(-v0m));
        float g1 = 1.f / (1.f + expf(-v1m));
        int s0 = atomicAdd(&d_cnt[i0], 1);
        int s1 = atomicAdd(&d_cnt[i1], 1);
        d_tok[i0][s0] = t; d_gate[i0][s0] = g0; d_eslot[t][0] = i0 * NTOK + s0;
        d_tok[i1][s1] = t; d_gate[i1][s1] = g1; d_eslot[t][1] = i1 * NTOK + s1;
    }
}

// ---------------- preprocessing ----------------
// 3 shared-weight arrays fp32 [N,K] -> fp16 perm (one 16-group per thread)
__global__ void round_perm3(const float* __restrict__ s0, __half* __restrict__ d0,
                            const float* __restrict__ s1, __half* __restrict__ d1,
                            const float* __restrict__ s2, __half* __restrict__ d2) {
    const float* src = (blockIdx.y == 0) ? s0 : (blockIdx.y == 1) ? s1 : s2;
    __half*      dst = (blockIdx.y == 0) ? d0 : (blockIdx.y == 1) ? d1 : d2;
    long long g = (long long)blockIdx.x * 256 + threadIdx.x;
    const float4* s4 = (const float4*)src;
    float4 v0 = s4[4 * g], v1 = s4[4 * g + 1], v2 = s4[4 * g + 2], v3 = s4[4 * g + 3];
    uint4 o0, o1;
    o0.x = h2u(v0.x, v0.y); o0.y = h2u(v2.x, v2.y);
    o0.z = h2u(v0.z, v0.w); o0.w = h2u(v2.z, v2.w);
    o1.x = h2u(v1.x, v1.y); o1.y = h2u(v3.x, v3.y);
    o1.z = h2u(v1.z, v1.w); o1.w = h2u(v3.z, v3.w);
    ((uint4*)dst)[2 * g] = o0; ((uint4*)dst)[2 * g + 1] = o1;
}
// dst[z][c][perm16(r)] = h(src[z][r][c])
__global__ void transpose_h_perm(const float* __restrict__ src, __half* __restrict__ dst,
                                 int R, int C) {
    __shared__ float tile[32][33];
    long long zi = (long long)blockIdx.z * R * C;
    int r0 = blockIdx.y * 32, c0 = blockIdx.x * 32;
    int tx = threadIdx.x, ty = threadIdx.y;
#pragma unroll
    for (int i = 0; i < 32; i += 8)
        tile[ty + i][tx] = src[zi + (long long)(r0 + ty + i) * C + c0 + tx];
    __syncthreads();
    int rp = r0 + (tx & 16) + ph16(tx & 15);
#pragma unroll
    for (int i = 0; i < 32; i += 8)
        dst[zi + (long long)(c0 + ty + i) * R + rp] = __float2half_rn(tile[tx][ty + i]);
}

// ---------------- phase 1: fused SwiGLU GEMMs (fp16, templated expert/shared) ---
template <bool EXPERT>
__global__ __launch_bounds__(128) void phase1_kernel(
    const __half* __restrict__ xr, const __half* __restrict__ guT,
    const __half* __restrict__ sgw, const __half* __restrict__ suw,
    __half* __restrict__ hid, __half* __restrict__ sh)
{
    const int bid = blockIdx.x;
    const __half *B1, *B2;
    __half* C; int ldc, z = 0, bm, bn;
    if (EXPERT) {
        z = bid >> 8; int rem = bid & 255; bm = rem >> 3; bn = rem & 7;
        if (bm * BM >= d_cnt[z]) return;
        B1 = guT + (long long)z * 2 * HDIM * CDIM + (long long)(bn * 64) * CDIM;
        B2 = B1 + (long long)HDIM * CDIM;
        C  = hid + (long long)z * NTOK * HDIM;
        ldc = HDIM;
    } else {
        bm = bid >> 5; bn = bid & 31;
        B1 = sgw + (long long)(bn * 64) * CDIM;
        B2 = suw + (long long)(bn * 64) * CDIM;
        C  = sh;
        ldc = HSDIM;
    }
    const int K = CDIM;

    extern __shared__ __align__(16) __half smem[];
    __half* sA = smem;
    __half* sB = smem + 2 * STGH;

    const int tid = threadIdx.x, lane = tid & 31, w = tid >> 5;
    const int ly = lane >> 2, lx = lane & 3;
    const int wm = w >> 1, wn = w & 1;

    const __half* aPtr[8];
    const __half* bPtr[8];
    const int rbase = tid >> 3, kc = (tid & 7) * 8;
#pragma unroll
    for (int c = 0; c < 8; c++) {
        int row = rbase + 16 * c;
        long long arow = EXPERT ? (long long)d_tok[z][bm * BM + row] : (long long)(bm * BM + row);
        aPtr[c] = xr + arow * K;
        bPtr[c] = ((row < 64) ? (B1 + (long long)row * K) : (B2 + (long long)(row - 64) * K));
    }
    auto loadStage = [&](int st, int k0) {
        __half* dA = sA + st * STGH;
        __half* dB = sB + st * STGH;
#pragma unroll
        for (int c = 0; c < 8; c++) {
            int row = rbase + 16 * c;
            cp16(dA + row * AST2 + kc, aPtr[c] + k0 + kc);
            cp16(dB + row * AST2 + kc, bPtr[c] + k0 + kc);
        }
        asm volatile("cp.async.commit_group;");
    };

    float accG[4][4][4], accU[4][4][4];
#pragma unroll
    for (int a = 0; a < 4; a++)
#pragma unroll
        for (int b = 0; b < 4; b++)
#pragma unroll
            for (int q = 0; q < 4; q++) { accG[a][b][q] = 0.f; accU[a][b][q] = 0.f; }

    const int nk = K / BKH;
    loadStage(0, 0);

    for (int kt = 0; kt < nk; kt++) {
        const int st = kt & 1;
        asm volatile("cp.async.wait_group 0;");
        __syncthreads();
        if (kt + 1 < nk) loadStage((kt + 1) & 1, (kt + 1) * BKH);

        const __half* cA = sA + st * STGH;
        const __half* cB = sB + st * STGH;
#pragma unroll
        for (int kg = 0; kg < 4; kg++) {
            const int kb = kg * 16 + lx * 4;
            uint32_t af[4][4], bg[4][2], bu[4][2];
#pragma unroll
            for (int im = 0; im < 4; im++) {
                int r = wm * 64 + im * 16;
                uint2 v0 = *(const uint2*)(cA + (r     + ly) * AST2 + kb);
                uint2 v1 = *(const uint2*)(cA + (r + 8 + ly) * AST2 + kb);
                af[im][0] = v0.x; af[im][1] = v1.x; af[im][2] = v0.y; af[im][3] = v1.y;
            }
#pragma unroll
            for (int in = 0; in < 4; in++) {
                int cn = wn * 32 + in * 8 + ly;
                uint2 g = *(const uint2*)(cB + cn * AST2 + kb);
                uint2 u = *(const uint2*)(cB + (64 + cn) * AST2 + kb);
                bg[in][0] = g.x; bg[in][1] = g.y;
                bu[in][0] = u.x; bu[in][1] = u.y;
            }
#pragma unroll
            for (int im = 0; im < 4; im++)
#pragma unroll
                for (int in = 0; in < 4; in++) {
                    mma16(accG[im][in], af[im], bg[in]);
                    mma16(accU[im][in], af[im], bu[in]);
                }
        }
    }

    // epilogue: out = fp16(silu(g)*u), perm16 layout
#pragma unroll
    for (int im = 0; im < 4; im++) {
        int rr = bm * BM + wm * 64 + im * 16 + ly;
#pragma unroll
        for (int in = 0; in < 4; in++) {
            int G   = wn * 2 + (in >> 1);
            int pos = lx * 4 + (in & 1) * 2;
            long long off = (long long)rr * ldc + bn * 64 + G * 16 + pos;
            float* g = accG[im][in];
            float* u = accU[im][in];
            *(uint32_t*)(C + off)             = h2u(silu_f(g[0]) * u[0], silu_f(g[1]) * u[1]);
            *(uint32_t*)(C + off + 8LL * ldc) = h2u(silu_f(g[2]) * u[2], silu_f(g[3]) * u[3]);
        }
    }
}

// ---------------- phase 2: down GEMMs (fp16, templated expert/shared) ------------
template <bool EXPERT>
__global__ __launch_bounds__(128) void phase2_kernel(
    const __half* __restrict__ hid, const __half* __restrict__ dwT,
    const __half* __restrict__ sh,  const __half* __restrict__ sdw,
    float* __restrict__ pair, float* __restrict__ out)
{
    const int bid = blockIdx.x;
    const __half *A, *B; const float* gate; float* C;
    int K, z = 0, bm, bn;
    if (EXPERT) {
        z = bid >> 8; int rem = bid & 255; bm = rem >> 3; bn = rem & 7;
        if (bm * BM >= d_cnt[z]) return;
        A = hid + (long long)z * NTOK * HDIM;
        K = HDIM;
        B = dwT + (long long)z * CDIM * HDIM + (long long)(bn * 128) * HDIM;
        C = pair + (long long)z * NTOK * CDIM;
        gate = d_gate[z];
    } else {
        bm = bid >> 3; bn = bid & 7;
        A = sh; K = HSDIM;
        B = sdw + (long long)(bn * 128) * HSDIM;
        C = out;
        gate = nullptr;
    }

    extern __shared__ __align__(16) __half smem[];
    __half* sA = smem;
    __half* sB = smem + 2 * STGH;

    const int tid = threadIdx.x, lane = tid & 31, w = tid >> 5;
    const int ly = lane >> 2, lx = lane & 3;
    const int wm = w >> 1, wn = w & 1;

    const int rbase = tid >> 3, kc = (tid & 7) * 8;
    const __half* aBase = A + (long long)(bm * BM + rbase) * K;
    const __half* bBase = B + (long long)rbase * K;

    auto loadStage = [&](int st, int k0) {
        __half* dA = sA + st * STGH;
        __half* dB = sB + st * STGH;
#pragma unroll
        for (int c = 0; c < 8; c++) {
            int row = rbase + 16 * c;
            cp16(dA + row * AST2 + kc, aBase + (long long)(16 * c) * K + k0 + kc);
            cp16(dB + row * AST2 + kc, bBase + (long long)(16 * c) * K + k0 + kc);
        }
        asm volatile("cp.async.commit_group;");
    };

    float acc[4][8][4];
#pragma unroll
    for (int a = 0; a < 4; a++)
#pragma unroll
        for (int b = 0; b < 8; b++)
#pragma unroll
            for (int q = 0; q < 4; q++) acc[a][b][q] = 0.f;

    const int nk = K / BKH;
    loadStage(0, 0);

    for (int kt = 0; kt < nk; kt++) {
        const int st = kt & 1;
        asm volatile("cp.async.wait_group 0;");
        __syncthreads();
        if (kt + 1 < nk) loadStage((kt + 1) & 1, (kt + 1) * BKH);

        const __half* cA = sA + st * STGH;
        const __half* cB = sB + st * STGH;
#pragma unroll
        for (int kg = 0; kg < 4; kg++) {
            const int kb = kg * 16 + lx * 4;
            uint32_t af[4][4], bf[8][2];
#pragma unroll
            for (int im = 0; im < 4; im++) {
                int r = wm * 64 + im * 16;
                uint2 v0 = *(const uint2*)(cA + (r     + ly) * AST2 + kb);
                uint2 v1 = *(const uint2*)(cA + (r + 8 + ly) * AST2 + kb);
                af[im][0] = v0.x; af[im][1] = v1.x; af[im][2] = v0.y; af[im][3] = v1.y;
            }
#pragma unroll
            for (int in = 0; in < 8; in++) {
                int cn = wn * 64 + in * 8 + ly;
                uint2 bb = *(const uint2*)(cB + cn * AST2 + kb);
                bf[in][0] = bb.x; bf[in][1] = bb.y;
            }
#pragma unroll
            for (int im = 0; im < 4; im++)
#pragma unroll
                for (int in = 0; in < 8; in++)
                    mma16(acc[im][in], af[im], bf[in]);
        }
    }

#pragma unroll
    for (int im = 0; im < 4; im++) {
        int rr = bm * BM + wm * 64 + im * 16 + ly;
        float s0 = gate ? gate[rr] : 1.f;
        float s1 = gate ? gate[rr + 8] : 1.f;
#pragma unroll
        for (int in = 0; in < 8; in++) {
            long long base = (long long)rr * CDIM + bn * 128 + wn * 64 + in * 8 + lx * 2;
            *(float2*)(C + base)              = make_float2(acc[im][in][0] * s0, acc[im][in][1] * s0);
            *(float2*)(C + base + 8LL * CDIM) = make_float2(acc[im][in][2] * s1, acc[im][in][3] * s1);
        }
    }
}

// ---------------- final combine: out += gated expert pair ----------------
__global__ void combine_kernel(float* __restrict__ out) {
    long long i = (long long)blockIdx.x * 256 + threadIdx.x;
    int t = (int)(i >> 8), j = (int)(i & 255);
    int es0 = d_eslot[t][0], es1 = d_eslot[t][1];
    float4 o  = ((float4*)out)[i];
    float4 p0 = ((const float4*)d_pair)[(long long)es0 * 256 + j];
    float4 p1 = ((const float4*)d_pair)[(long long)es1 * 256 + j];
    o.x += p0.x + p1.x; o.y += p0.y + p1.y;
    o.z += p0.z + p1.z; o.w += p0.w + p1.w;
    ((float4*)out)[i] = o;
}

// ---------------- launch ----------------
extern "C" void kernel_launch(void* const* d_in, const int* in_sizes, int n_in,
                              void* d_out, int out_size) {
    const float* x   = (const float*)d_in[0];
    const float* rw  = (const float*)d_in[1];
    const float* guw = (const float*)d_in[2];
    const float* dw  = (const float*)d_in[3];
    const float* sgw = (const float*)d_in[4];
    const float* suw = (const float*)d_in[5];
    const float* sdw = (const float*)d_in[6];
    float* out = (float*)d_out;

    void* a;
    float* p_pair;
    __half *p_hid, *p_sh, *p_xr, *p_guT, *p_dwT, *p_sgwr, *p_suwr, *p_sdwr;
    cudaGetSymbolAddress(&a, d_hid);  p_hid  = (__half*)a;
    cudaGetSymbolAddress(&a, d_pair); p_pair = (float*)a;
    cudaGetSymbolAddress(&a, d_sh);   p_sh   = (__half*)a;
    cudaGetSymbolAddress(&a, d_xr);   p_xr   = (__half*)a;
    cudaGetSymbolAddress(&a, d_guT);  p_guT  = (__half*)a;
    cudaGetSymbolAddress(&a, d_dwT);  p_dwT  = (__half*)a;
    cudaGetSymbolAddress(&a, d_sgwr); p_sgwr = (__half*)a;
    cudaGetSymbolAddress(&a, d_suwr); p_suwr = (__half*)a;
    cudaGetSymbolAddress(&a, d_sdwr); p_sdwr = (__half*)a;
    void* cntAddr; cudaGetSymbolAddress(&cntAddr, d_cnt);

    static cudaStream_t s1 = nullptr, s2 = nullptr;
    static cudaEvent_t ev0 = nullptr, evG = nullptr, evD = nullptr, evP = nullptr,
                       evR = nullptr, evS = nullptr;
    if (!s1) {
        cudaStreamCreateWithFlags(&s1, cudaStreamNonBlocking);
        cudaStreamCreateWithFlags(&s2, cudaStreamNonBlocking);
        cudaEventCreateWithFlags(&ev0, cudaEventDisableTiming);
        cudaEventCreateWithFlags(&evG, cudaEventDisableTiming);
        cudaEventCreateWithFlags(&evD, cudaEventDisableTiming);
        cudaEventCreateWithFlags(&evP, cudaEventDisableTiming);
        cudaEventCreateWithFlags(&evR, cudaEventDisableTiming);
        cudaEventCreateWithFlags(&evS, cudaEventDisableTiming);
        cudaFuncSetAttribute(phase1_kernel<true >, cudaFuncAttributeMaxDynamicSharedMemorySize, SMEMB);
        cudaFuncSetAttribute(phase1_kernel<false>, cudaFuncAttributeMaxDynamicSharedMemorySize, SMEMB);
        cudaFuncSetAttribute(phase2_kernel<true >, cudaFuncAttributeMaxDynamicSharedMemorySize, SMEMB);
        cudaFuncSetAttribute(phase2_kernel<false>, cudaFuncAttributeMaxDynamicSharedMemorySize, SMEMB);
    }

    // ---- fork point ----
    cudaEventRecord(ev0, 0);
    cudaStreamWaitEvent(s1, ev0, 0);

    // side stream s1: ordered so earliest consumers unblock first
    transpose_h_perm<<<dim3(2 * HDIM / 32, CDIM / 32, ENUM), dim3(32, 8), 0, s1>>>(guw, p_guT, CDIM, 2 * HDIM);
    cudaEventRecord(evG, s1);
    round_perm3<<<dim3(HSDIM * CDIM / 16 / 256, 3), 256, 0, s1>>>(sgw, p_sgwr, suw, p_suwr, sdw, p_sdwr);
    cudaEventRecord(evP, s1);
    transpose_h_perm<<<dim3(CDIM / 32, HDIM / 32, ENUM), dim3(32, 8), 0, s1>>>(dw, p_dwT, HDIM, CDIM);
    cudaEventRecord(evD, s1);

    // main stream: router (emits fp16-perm x + routing tables)
    cudaMemsetAsync(cntAddr, 0, sizeof(int) * ENUM, 0);
    router_kernel<<<NTOK / 4, 256, 0, 0>>>(x, rw, p_xr);
    cudaEventRecord(evR, 0);

    // expert chain on main stream: p1e -> p2e
    cudaStreamWaitEvent(0, evG, 0);
    phase1_kernel<true><<<2048, 128, SMEMB, 0>>>(p_xr, p_guT, p_sgwr, p_suwr, p_hid, p_sh);
    cudaStreamWaitEvent(0, evD, 0);
    phase2_kernel<true><<<2048, 128, SMEMB, 0>>>(p_hid, p_dwT, p_sh, p_sdwr, p_pair, out);

    // shared chain on s2: p1s -> p2s (writes out base)
    cudaStreamWaitEvent(s2, evR, 0);
    cudaStreamWaitEvent(s2, evP, 0);
    phase1_kernel<false><<<1024, 128, SMEMB, s2>>>(p_xr, p_guT, p_sgwr, p_suwr, p_hid, p_sh);
    phase2_kernel<false><<<256, 128, SMEMB, s2>>>(p_hid, p_dwT, p_sh, p_sdwr, p_pair, out);
    cudaEventRecord(evS, s2);

    // ---- join: combine after both chains ----
    cudaStreamWaitEvent(0, evS, 0);
    combine_kernel<<<NTOK * CDIM / 4 / 256, 256, 0, 0>>>(out);

    (void)in_sizes; (void)n_in; (void)out_size;
}